// round 15
// baseline (speedup 1.0000x reference)
#include <cuda_runtime.h>
#include <cuda_fp16.h>
#include <cstdint>

// B=2, S=2048, D=1024, H=16, DH=64
#define BB 2
#define SS 2048
#define DD 1024
#define HH 16
#define DHH 64
#define MM (BB * SS) /* 4096 rows */
#define HSZ ((size_t)BB * HH * SS * DHH)

// ---------------------------------------------------------------------------
// Scratch: pure fp16 1-term scheme.
// ---------------------------------------------------------------------------
__device__ __half gXh[3][(size_t)MM * DD];      // sources
__device__ __half gWh[4][(size_t)DD * DD];      // weights
__device__ __half gQh[HSZ];                     // Q (x0.125)
__device__ __half gKh[HSZ];
__device__ __half gVh[HSZ];
__device__ __half gCh[(size_t)MM * DD];         // ctx
__device__ float g_res[(size_t)MM * DD];        // fp32 resid sum

// ---------------------------------------------------------------------------
// Helpers
// ---------------------------------------------------------------------------
__device__ __forceinline__ uint32_t smem_u32(const void* p) {
    uint32_t a;
    asm("{ .reg .u64 t; cvta.to.shared.u64 t, %1; cvt.u32.u64 %0, t; }" : "=r"(a) : "l"(p));
    return a;
}
__device__ __forceinline__ uint32_t pack_f16(float a, float b) {
    __half2 h = __floats2half2_rn(a, b);
    return *(uint32_t*)&h;
}
__device__ __forceinline__ void cp16(uint32_t dst, const void* src) {
    asm volatile("cp.async.cg.shared.global [%0], [%1], 16;" :: "r"(dst), "l"(src) : "memory");
}
#define CP_COMMIT() asm volatile("cp.async.commit_group;" ::: "memory")
#define CP_WAIT0()  asm volatile("cp.async.wait_group 0;" ::: "memory")
#define CP_WAIT1()  asm volatile("cp.async.wait_group 1;" ::: "memory")
#define LDSM4(R0, R1, R2, R3, ADDR) \
    asm volatile("ldmatrix.sync.aligned.m8n8.x4.shared.b16 {%0,%1,%2,%3}, [%4];" \
        : "=r"(R0), "=r"(R1), "=r"(R2), "=r"(R3) : "r"(ADDR))
#define LDSM4T(R0, R1, R2, R3, ADDR) \
    asm volatile("ldmatrix.sync.aligned.m8n8.x4.trans.shared.b16 {%0,%1,%2,%3}, [%4];" \
        : "=r"(R0), "=r"(R1), "=r"(R2), "=r"(R3) : "r"(ADDR))
#define MMA_F16(D, A, B0, B1) \
    asm volatile("mma.sync.aligned.m16n8k16.row.col.f32.f16.f16.f32 " \
        "{%0,%1,%2,%3}, {%4,%5,%6,%7}, {%8,%9}, {%0,%1,%2,%3};" \
        : "+f"((D)[0]), "+f"((D)[1]), "+f"((D)[2]), "+f"((D)[3]) \
        : "r"((A)[0]), "r"((A)[1]), "r"((A)[2]), "r"((A)[3]), "r"(B0), "r"(B1))

// ---------------------------------------------------------------------------
// split_pass: fp32 -> fp16 (truncate). z 0..2: sources. z 3..6: weights.
// ---------------------------------------------------------------------------
__global__ __launch_bounds__(256) void split_pass(
    const float* s0, const float* s1, const float* s2,
    const float* w0, const float* w1, const float* w2, const float* w3) {
    const int z = blockIdx.z;
    const size_t idx = ((size_t)blockIdx.x * 256 + threadIdx.x) * 4;
    const float* src;
    __half* dst;
    if (z < 3) {
        if (idx >= (size_t)MM * DD) return;
        src = (z == 0) ? s0 : (z == 1) ? s1 : s2;
        dst = gXh[z];
    } else {
        if (idx >= (size_t)DD * DD) return;
        const int w = z - 3;
        src = (w == 0) ? w0 : (w == 1) ? w1 : (w == 2) ? w2 : w3;
        dst = gWh[w];
    }
    float4 x = *(const float4*)(src + idx);
    uint32_t* hp = (uint32_t*)(dst + idx);
    hp[0] = pack_f16(x.x, x.y);
    hp[1] = pack_f16(x.z, x.w);
}

// ---------------------------------------------------------------------------
// HMMA GEMM, fp16 1-term, cp.async double buffer, BK=64 (16 iterations).
// CTA tile 128x128, 8 warps (4m x 2n). 64 MMAs per warp between syncs.
// WHICH 0: Q (x0.125). 1: K. 2: V. 3: out-proj (fp32 + resid).
// ---------------------------------------------------------------------------
#define GPITCH 144
#define GSTAGE (2 * 128 * GPITCH)          /* 36864 B per stage: A + B */
#define GMATS  (128 * GPITCH)              /* 18432 B per matrix */
#define GSMEM  (2 * GSTAGE)                /* 73728 B */

template <int WHICH>
__device__ __forceinline__ void gemm_core(const __half* __restrict__ Xh,
                                          const __half* __restrict__ Wh,
                                          const float* __restrict__ bias,
                                          const float* __restrict__ resid) {
    extern __shared__ __align__(16) unsigned char dynsm[];
    const uint32_t s0 = smem_u32(dynsm);

    const int tid = threadIdx.x;
    const int lane = tid & 31;
    const int wid = tid >> 5;
    const int wm = wid & 3;
    const int wn = wid >> 2;
    const int mBase = blockIdx.y * 128;
    const int nBase = blockIdx.x * 128;

    float acc[2][8][4];
#pragma unroll
    for (int i = 0; i < 2; i++)
#pragma unroll
        for (int j = 0; j < 8; j++)
#pragma unroll
            for (int c = 0; c < 4; c++) acc[i][j][c] = 0.0f;

    const int mat = lane >> 3;
    const int rin = lane & 7;
    const int sRow = tid >> 3;           // 0..31
    const int sC = tid & 7;              // 16B chunk within 128B row-data

    auto stage = [&](int k0, int buf) {
        const uint32_t sb = s0 + (uint32_t)(buf * GSTAGE);
#pragma unroll
        for (int i = 0; i < 4; i++) {
            const int row = i * 32 + sRow;
            const uint32_t d = sb + (uint32_t)(row * GPITCH + sC * 16);
            cp16(d,         Xh + (size_t)(mBase + row) * DD + k0 + sC * 8);
            cp16(d + GMATS, Wh + (size_t)(nBase + row) * DD + k0 + sC * 8);
        }
    };

    stage(0, 0);
    CP_COMMIT();

    for (int it = 0; it < 16; it++) {
        if (it < 15) {
            stage((it + 1) * 64, (it + 1) & 1);
            CP_COMMIT();
            CP_WAIT1();
        } else {
            CP_WAIT0();
        }
        __syncthreads();

        const uint32_t sb = s0 + (uint32_t)((it & 1) * GSTAGE);
        const uint32_t sA = sb, sB = sb + GMATS;

#pragma unroll
        for (int ks = 0; ks < 4; ks++) {
            const uint32_t acol = (uint32_t)((ks * 16 + (mat >> 1) * 8) * 2);
            uint32_t ah[2][4];
#pragma unroll
            for (int bm = 0; bm < 2; bm++) {
                const uint32_t ra = (uint32_t)((wm * 32 + bm * 16 + (mat & 1) * 8 + rin) * GPITCH);
                LDSM4(ah[bm][0], ah[bm][1], ah[bm][2], ah[bm][3], sA + ra + acol);
            }
            const uint32_t bcol = (uint32_t)((ks * 16 + (mat & 1) * 8) * 2);
            uint32_t bh[4][4];
#pragma unroll
            for (int bn = 0; bn < 4; bn++) {
                const uint32_t rb = (uint32_t)((wn * 64 + bn * 16 + (mat >> 1) * 8 + rin) * GPITCH);
                LDSM4(bh[bn][0], bh[bn][1], bh[bn][2], bh[bn][3], sB + rb + bcol);
            }
#pragma unroll
            for (int bn = 0; bn < 4; bn++)
#pragma unroll
                for (int bm = 0; bm < 2; bm++)
#pragma unroll
                    for (int nf = 0; nf < 2; nf++)
                        MMA_F16(acc[bm][bn * 2 + nf], ah[bm], bh[bn][nf * 2], bh[bn][nf * 2 + 1]);
        }
        __syncthreads();
    }

    const int g = lane >> 2;
    const int t2 = (lane & 3) * 2;
#pragma unroll
    for (int bm = 0; bm < 2; bm++) {
#pragma unroll
        for (int nf = 0; nf < 8; nf++) {
            const int n0 = nBase + wn * 64 + nf * 8 + t2;
            const float b0 = bias[n0], b1 = bias[n0 + 1];
#pragma unroll
            for (int half_ = 0; half_ < 2; half_++) {
                const int m = mBase + wm * 32 + bm * 16 + g + half_ * 8;
                float v0 = acc[bm][nf][half_ * 2 + 0] + b0;
                float v1 = acc[bm][nf][half_ * 2 + 1] + b1;
                if (WHICH < 3) {
                    if (WHICH == 0) { v0 *= 0.125f; v1 *= 0.125f; }
                    const int bI = m >> 11;
                    const int s = m & (SS - 1);
                    const int h = n0 >> 6;
                    const int dh = n0 & 63;
                    const size_t idx = (((size_t)(bI * HH + h)) * SS + s) * DHH + dh;
                    __half* dst = (WHICH == 0) ? gQh : (WHICH == 1) ? gKh : gVh;
                    *(uint32_t*)(dst + idx) = pack_f16(v0, v1);
                } else {
                    const size_t off = (size_t)m * DD + n0;
                    float2 rv = *(const float2*)(resid + off);
                    float2 t; t.x = v0 + rv.x; t.y = v1 + rv.y;
                    *(float2*)(g_res + off) = t;
                }
            }
        }
    }
}

__global__ __launch_bounds__(256) void hmma_gemm_qkv(const float* __restrict__ bQ,
                                                     const float* __restrict__ bK,
                                                     const float* __restrict__ bV) {
    if (blockIdx.z == 0)      gemm_core<0>(gXh[0], gWh[0], bQ, nullptr);
    else if (blockIdx.z == 1) gemm_core<1>(gXh[1], gWh[1], bK, nullptr);
    else                      gemm_core<2>(gXh[2], gWh[2], bV, nullptr);
}

__global__ __launch_bounds__(256) void hmma_gemm_o(const float* __restrict__ bO,
                                                   const float* __restrict__ resid) {
    gemm_core<3>(gCh, gWh[3], bO, resid);
}

// ---------------------------------------------------------------------------
// HMMA flash attention (causal), pure fp16, 128-key stages processed as two
// 64-key sub-chunks (same registers, half the syncs / cp groups).
// 512 CTAs (bh x 16 qtiles), 8 warps x 16 q-rows.
// ---------------------------------------------------------------------------
#define APITCH 144
#define AMATS  (128 * APITCH)              /* 18432 B per matrix (128 keys) */
#define ASTAGE (2 * AMATS)                 /* 36864 B per stage: K + V */
#define ASMEM  (2 * ASTAGE)                /* 73728 B */

__global__ __launch_bounds__(256) void attn_mma_kernel() {
    extern __shared__ __align__(16) unsigned char dynsm[];
    const uint32_t base = smem_u32(dynsm);

    const int bh = blockIdx.x >> 4;
    const int qt = 15 - (blockIdx.x & 15);
    const int tid = threadIdx.x;
    const int lane = tid & 31;
    const int wid = tid >> 5;
    const int qBase = qt * 128;
    const int mat = lane >> 3;
    const int rin = lane & 7;
    const int g = lane >> 2;
    const int t2 = (lane & 3) * 2;

    const size_t headOff = (size_t)bh * SS * DHH;
    const int sRow = tid >> 3;            // 0..31
    const int sC = tid & 7;               // 16B chunk (8 halves) in 128B row

    // ---- prologue: stage Q (128 rows) at base ----
#pragma unroll
    for (int i = 0; i < 4; i++) {
        const int row = i * 32 + sRow;
        const uint32_t d = base + (uint32_t)(row * APITCH + sC * 16);
        cp16(d, gQh + headOff + (size_t)(qBase + row) * DHH + sC * 8);
    }
    CP_COMMIT();
    CP_WAIT0();
    __syncthreads();

    uint32_t qh[4][4];
#pragma unroll
    for (int kf = 0; kf < 4; kf++) {
        const uint32_t ra = (uint32_t)((wid * 16 + (mat & 1) * 8 + rin) * APITCH);
        const uint32_t acol = (uint32_t)((kf * 16 + (mat >> 1) * 8) * 2);
        LDSM4(qh[kf][0], qh[kf][1], qh[kf][2], qh[kf][3], base + ra + acol);
    }
    __syncthreads();                      // Q reads done; buffers free

    auto stageKV = [&](int c0, int buf) { // 128 keys per stage
        const uint32_t sb = base + (uint32_t)(buf * ASTAGE);
#pragma unroll
        for (int i = 0; i < 4; i++) {
            const int row = i * 32 + sRow;
            const uint32_t d = sb + (uint32_t)(row * APITCH + sC * 16);
            const size_t off = headOff + (size_t)(c0 + row) * DHH + sC * 8;
            cp16(d,         gKh + off);
            cp16(d + AMATS, gVh + off);
        }
    };

    stageKV(0, 0);
    CP_COMMIT();

    float oacc[8][4];
#pragma unroll
    for (int f = 0; f < 8; f++)
#pragma unroll
        for (int c = 0; c < 4; c++) oacc[f][c] = 0.0f;
    float mA = -1e30f, mB = -1e30f, lA = 0.0f, lB = 0.0f;

    const int qw0 = qBase + wid * 16;
    const int nst = qt + 1;               // 128-key stages

    for (int st = 0; st < nst; st++) {
        if (st + 1 < nst) {
            stageKV((st + 1) * 128, (st + 1) & 1);
            CP_COMMIT();
            CP_WAIT1();
        } else {
            CP_WAIT0();
        }
        __syncthreads();

        const uint32_t sb = base + (uint32_t)((st & 1) * ASTAGE);
        const uint32_t Kh = sb, Vh = sb + AMATS;

#pragma unroll
        for (int hf = 0; hf < 2; hf++) {  // two 64-key sub-chunks
            const int c0 = st * 128 + hf * 64;
            if (c0 > qw0 + 15) break;

            // ---- S = Q * K^T ----
            float sacc[8][4];
#pragma unroll
            for (int f = 0; f < 8; f++)
#pragma unroll
                for (int c = 0; c < 4; c++) sacc[f][c] = 0.0f;

#pragma unroll
            for (int ks = 0; ks < 4; ks++) {
                const uint32_t bcol = (uint32_t)((ks * 16 + (mat & 1) * 8) * 2);
                uint32_t kbh[4][4];
#pragma unroll
                for (int bn = 0; bn < 4; bn++) {
                    const uint32_t rb = (uint32_t)((hf * 64 + bn * 16 + (mat >> 1) * 8 + rin) * APITCH);
                    LDSM4(kbh[bn][0], kbh[bn][1], kbh[bn][2], kbh[bn][3], Kh + rb + bcol);
                }
#pragma unroll
                for (int bn = 0; bn < 4; bn++)
#pragma unroll
                    for (int nf = 0; nf < 2; nf++)
                        MMA_F16(sacc[bn * 2 + nf], qh[ks], kbh[bn][nf * 2], kbh[bn][nf * 2 + 1]);
            }

            // ---- causal mask ----
            const int rowA = qw0 + g;
            const int rowB = rowA + 8;
            if (c0 + 63 > qw0) {
#pragma unroll
                for (int f = 0; f < 8; f++) {
                    const int k0e = c0 + f * 8 + t2;
                    if (k0e > rowA)     sacc[f][0] = -1e30f;
                    if (k0e + 1 > rowA) sacc[f][1] = -1e30f;
                    if (k0e > rowB)     sacc[f][2] = -1e30f;
                    if (k0e + 1 > rowB) sacc[f][3] = -1e30f;
                }
            }

            // ---- online softmax ----
            float tmA = -1e30f, tmB = -1e30f;
#pragma unroll
            for (int f = 0; f < 8; f++) {
                tmA = fmaxf(tmA, fmaxf(sacc[f][0], sacc[f][1]));
                tmB = fmaxf(tmB, fmaxf(sacc[f][2], sacc[f][3]));
            }
            tmA = fmaxf(tmA, __shfl_xor_sync(0xffffffffu, tmA, 1));
            tmA = fmaxf(tmA, __shfl_xor_sync(0xffffffffu, tmA, 2));
            tmB = fmaxf(tmB, __shfl_xor_sync(0xffffffffu, tmB, 1));
            tmB = fmaxf(tmB, __shfl_xor_sync(0xffffffffu, tmB, 2));

            const float mnA = fmaxf(mA, tmA);
            const float mnB = fmaxf(mB, tmB);
            const float corrA = __expf(mA - mnA);
            const float corrB = __expf(mB - mnB);
            mA = mnA; mB = mnB;

            float sA = 0.0f, sB = 0.0f;
            uint32_t h01[8], h23[8];
#pragma unroll
            for (int f = 0; f < 8; f++) {
                float e0 = __expf(sacc[f][0] - mA);
                float e1 = __expf(sacc[f][1] - mA);
                float e2 = __expf(sacc[f][2] - mB);
                float e3 = __expf(sacc[f][3] - mB);
                sA += e0 + e1; sB += e2 + e3;
                h01[f] = pack_f16(e0, e1);
                h23[f] = pack_f16(e2, e3);
            }
            sA += __shfl_xor_sync(0xffffffffu, sA, 1);
            sA += __shfl_xor_sync(0xffffffffu, sA, 2);
            sB += __shfl_xor_sync(0xffffffffu, sB, 1);
            sB += __shfl_xor_sync(0xffffffffu, sB, 2);
            lA = lA * corrA + sA;
            lB = lB * corrB + sB;

#pragma unroll
            for (int f = 0; f < 8; f++) {
                oacc[f][0] *= corrA; oacc[f][1] *= corrA;
                oacc[f][2] *= corrB; oacc[f][3] *= corrB;
            }

            // ---- O += P * V ----
#pragma unroll
            for (int kf = 0; kf < 4; kf++) {
                uint32_t pah[4] = { h01[2 * kf], h23[2 * kf], h01[2 * kf + 1], h23[2 * kf + 1] };
                const uint32_t vaddr = (uint32_t)((hf * 64 + kf * 16 + (lane & 15)) * APITCH +
                                                  ((lane >> 4) * 8) * 2);
                uint32_t vbh[4][4];
#pragma unroll
                for (int dhg = 0; dhg < 4; dhg++) {
                    const uint32_t va = vaddr + (uint32_t)(dhg * 32);
                    LDSM4T(vbh[dhg][0], vbh[dhg][1], vbh[dhg][2], vbh[dhg][3], Vh + va);
                }
#pragma unroll
                for (int dhg = 0; dhg < 4; dhg++)
#pragma unroll
                    for (int nf = 0; nf < 2; nf++)
                        MMA_F16(oacc[dhg * 2 + nf], pah, vbh[dhg][nf * 2], vbh[dhg][nf * 2 + 1]);
            }
        }
        __syncthreads();
    }

    // ---- epilogue: normalize, write ctx fp16 ----
    const float invA = 1.0f / lA;
    const float invB = 1.0f / lB;
    const int b = bh >> 4;
    const int h = bh & 15;
    const int rowA = qw0 + g;
#pragma unroll
    for (int f = 0; f < 8; f++) {
        const int dh0 = f * 8 + t2;
        {
            const size_t off = ((size_t)(b * SS) + rowA) * DD + h * 64 + dh0;
            *(uint32_t*)(gCh + off) = pack_f16(oacc[f][0] * invA, oacc[f][1] * invA);
        }
        {
            const size_t off = ((size_t)(b * SS) + rowA + 8) * DD + h * 64 + dh0;
            *(uint32_t*)(gCh + off) = pack_f16(oacc[f][2] * invB, oacc[f][3] * invB);
        }
    }
}

// ---------------------------------------------------------------------------
// LayerNorm over D=1024 per row (biased var).
// ---------------------------------------------------------------------------
__global__ __launch_bounds__(256) void ln_kernel(const float* __restrict__ gamma,
                                                 const float* __restrict__ beta,
                                                 float* __restrict__ out) {
    const int row = blockIdx.x;
    const int tid = threadIdx.x;
    const float4 v = ((const float4*)(g_res + (size_t)row * DD))[tid];

    float s = v.x + v.y + v.z + v.w;
    float ss = v.x * v.x + v.y * v.y + v.z * v.z + v.w * v.w;
#pragma unroll
    for (int off = 16; off > 0; off >>= 1) {
        s  += __shfl_xor_sync(0xffffffffu, s, off);
        ss += __shfl_xor_sync(0xffffffffu, ss, off);
    }
    __shared__ float sh[18];
    const int wid = tid >> 5;
    if ((tid & 31) == 0) { sh[wid] = s; sh[8 + wid] = ss; }
    __syncthreads();
    if (tid == 0) {
        float ts = 0.f, tss = 0.f;
#pragma unroll
        for (int w = 0; w < 8; w++) { ts += sh[w]; tss += sh[8 + w]; }
        const float mu = ts * (1.0f / DD);
        const float var = tss * (1.0f / DD) - mu * mu;
        sh[16] = mu;
        sh[17] = rsqrtf(var + 1e-5f);
    }
    __syncthreads();
    const float mu = sh[16];
    const float rstd = sh[17];

    const float4 gv = ((const float4*)gamma)[tid];
    const float4 bv = ((const float4*)beta)[tid];
    float4 r;
    r.x = (v.x - mu) * rstd * gv.x + bv.x;
    r.y = (v.y - mu) * rstd * gv.y + bv.y;
    r.z = (v.z - mu) * rstd * gv.z + bv.z;
    r.w = (v.w - mu) * rstd * gv.w + bv.w;
    ((float4*)(out + (size_t)row * DD))[tid] = r;
}

// ---------------------------------------------------------------------------
// 0 Q_source, 1 K_source, 2 V_source, 3 padding_mask, 4 future_mask,
// 5 WQ, 6 bQ, 7 WK, 8 bK, 9 WV, 10 bV, 11 WO, 12 bO, 13 gamma, 14 beta
// ---------------------------------------------------------------------------
extern "C" void kernel_launch(void* const* d_in, const int* in_sizes, int n_in,
                              void* d_out, int out_size) {
    (void)in_sizes; (void)n_in; (void)out_size;
    const float* Qs    = (const float*)d_in[0];
    const float* Ksrc  = (const float*)d_in[1];
    const float* Vsrc  = (const float*)d_in[2];
    const float* WQ    = (const float*)d_in[5];
    const float* bQ    = (const float*)d_in[6];
    const float* WK    = (const float*)d_in[7];
    const float* bK    = (const float*)d_in[8];
    const float* WV    = (const float*)d_in[9];
    const float* bV    = (const float*)d_in[10];
    const float* WO    = (const float*)d_in[11];
    const float* bO    = (const float*)d_in[12];
    const float* gamma = (const float*)d_in[13];
    const float* beta  = (const float*)d_in[14];

    static bool attrDone = false;
    if (!attrDone) {
        cudaFuncSetAttribute(hmma_gemm_qkv, cudaFuncAttributeMaxDynamicSharedMemorySize, GSMEM);
        cudaFuncSetAttribute(hmma_gemm_o,   cudaFuncAttributeMaxDynamicSharedMemorySize, GSMEM);
        cudaFuncSetAttribute(attn_mma_kernel, cudaFuncAttributeMaxDynamicSharedMemorySize, ASMEM);
        attrDone = true;
    }

    split_pass<<<dim3(MM * DD / 1024, 1, 7), 256>>>(Qs, Ksrc, Vsrc, WQ, WK, WV, WO);

    dim3 qkvGrid(DD / 128, MM / 128, 3);   // (8, 32, 3) = 768 CTAs
    hmma_gemm_qkv<<<qkvGrid, 256, GSMEM>>>(bQ, bK, bV);
    attn_mma_kernel<<<BB * HH * 16, 256, ASMEM>>>();
    hmma_gemm_o<<<dim3(DD / 128, MM / 128), 256, GSMEM>>>(bO, Qs);
    ln_kernel<<<MM, 256>>>(gamma, beta, (float*)d_out);
}

// round 16
// speedup vs baseline: 1.0724x; 1.0724x over previous
#include <cuda_runtime.h>
#include <cuda_fp16.h>
#include <cstdint>

// B=2, S=2048, D=1024, H=16, DH=64
#define BB 2
#define SS 2048
#define DD 1024
#define HH 16
#define DHH 64
#define MM (BB * SS) /* 4096 rows */
#define HSZ ((size_t)BB * HH * SS * DHH)

// ---------------------------------------------------------------------------
// Scratch: pure fp16 1-term scheme.
// ---------------------------------------------------------------------------
__device__ __half gXh[3][(size_t)MM * DD];      // sources
__device__ __half gWh[4][(size_t)DD * DD];      // weights
__device__ __half gQh[HSZ];                     // Q (x0.125)
__device__ __half gKh[HSZ];
__device__ __half gVh[HSZ];
__device__ __half gCh[(size_t)MM * DD];         // ctx
__device__ float g_res[(size_t)MM * DD];        // fp32 resid sum

// ---------------------------------------------------------------------------
// Helpers
// ---------------------------------------------------------------------------
__device__ __forceinline__ uint32_t smem_u32(const void* p) {
    uint32_t a;
    asm("{ .reg .u64 t; cvta.to.shared.u64 t, %1; cvt.u32.u64 %0, t; }" : "=r"(a) : "l"(p));
    return a;
}
__device__ __forceinline__ uint32_t pack_f16(float a, float b) {
    __half2 h = __floats2half2_rn(a, b);
    return *(uint32_t*)&h;
}
__device__ __forceinline__ void cp16(uint32_t dst, const void* src) {
    asm volatile("cp.async.cg.shared.global [%0], [%1], 16;" :: "r"(dst), "l"(src) : "memory");
}
#define CP_COMMIT() asm volatile("cp.async.commit_group;" ::: "memory")
#define CP_WAIT0()  asm volatile("cp.async.wait_group 0;" ::: "memory")
#define CP_WAIT1()  asm volatile("cp.async.wait_group 1;" ::: "memory")
#define LDSM4(R0, R1, R2, R3, ADDR) \
    asm volatile("ldmatrix.sync.aligned.m8n8.x4.shared.b16 {%0,%1,%2,%3}, [%4];" \
        : "=r"(R0), "=r"(R1), "=r"(R2), "=r"(R3) : "r"(ADDR))
#define LDSM4T(R0, R1, R2, R3, ADDR) \
    asm volatile("ldmatrix.sync.aligned.m8n8.x4.trans.shared.b16 {%0,%1,%2,%3}, [%4];" \
        : "=r"(R0), "=r"(R1), "=r"(R2), "=r"(R3) : "r"(ADDR))
#define MMA_F16(D, A, B0, B1) \
    asm volatile("mma.sync.aligned.m16n8k16.row.col.f32.f16.f16.f32 " \
        "{%0,%1,%2,%3}, {%4,%5,%6,%7}, {%8,%9}, {%0,%1,%2,%3};" \
        : "+f"((D)[0]), "+f"((D)[1]), "+f"((D)[2]), "+f"((D)[3]) \
        : "r"((A)[0]), "r"((A)[1]), "r"((A)[2]), "r"((A)[3]), "r"(B0), "r"(B1))

// ---------------------------------------------------------------------------
// split_pass: fp32 -> fp16 (truncate). z 0..2: sources. z 3..6: weights.
// ---------------------------------------------------------------------------
__global__ __launch_bounds__(256) void split_pass(
    const float* s0, const float* s1, const float* s2,
    const float* w0, const float* w1, const float* w2, const float* w3) {
    const int z = blockIdx.z;
    const size_t idx = ((size_t)blockIdx.x * 256 + threadIdx.x) * 4;
    const float* src;
    __half* dst;
    if (z < 3) {
        if (idx >= (size_t)MM * DD) return;
        src = (z == 0) ? s0 : (z == 1) ? s1 : s2;
        dst = gXh[z];
    } else {
        if (idx >= (size_t)DD * DD) return;
        const int w = z - 3;
        src = (w == 0) ? w0 : (w == 1) ? w1 : (w == 2) ? w2 : w3;
        dst = gWh[w];
    }
    float4 x = *(const float4*)(src + idx);
    uint32_t* hp = (uint32_t*)(dst + idx);
    hp[0] = pack_f16(x.x, x.y);
    hp[1] = pack_f16(x.z, x.w);
}

// ---------------------------------------------------------------------------
// HMMA GEMM, fp16 1-term, cp.async double buffer, BK=64 (16 iterations).
// CTA tile 128x128, 8 warps (4m x 2n). __launch_bounds__(256,2) for 2 CTA/SM.
// WHICH 0: Q (x0.125). 1: K. 2: V. 3: out-proj (fp32 + resid).
// ---------------------------------------------------------------------------
#define GPITCH 144
#define GSTAGE (2 * 128 * GPITCH)          /* 36864 B per stage: A + B */
#define GMATS  (128 * GPITCH)              /* 18432 B per matrix */
#define GSMEM  (2 * GSTAGE)                /* 73728 B */

template <int WHICH>
__device__ __forceinline__ void gemm_core(const __half* __restrict__ Xh,
                                          const __half* __restrict__ Wh,
                                          const float* __restrict__ bias,
                                          const float* __restrict__ resid) {
    extern __shared__ __align__(16) unsigned char dynsm[];
    const uint32_t s0 = smem_u32(dynsm);

    const int tid = threadIdx.x;
    const int lane = tid & 31;
    const int wid = tid >> 5;
    const int wm = wid & 3;
    const int wn = wid >> 2;
    const int mBase = blockIdx.y * 128;
    const int nBase = blockIdx.x * 128;

    float acc[2][8][4];
#pragma unroll
    for (int i = 0; i < 2; i++)
#pragma unroll
        for (int j = 0; j < 8; j++)
#pragma unroll
            for (int c = 0; c < 4; c++) acc[i][j][c] = 0.0f;

    const int mat = lane >> 3;
    const int rin = lane & 7;
    const int sRow = tid >> 3;           // 0..31
    const int sC = tid & 7;              // 16B chunk within 128B row-data

    auto stage = [&](int k0, int buf) {
        const uint32_t sb = s0 + (uint32_t)(buf * GSTAGE);
#pragma unroll
        for (int i = 0; i < 4; i++) {
            const int row = i * 32 + sRow;
            const uint32_t d = sb + (uint32_t)(row * GPITCH + sC * 16);
            cp16(d,         Xh + (size_t)(mBase + row) * DD + k0 + sC * 8);
            cp16(d + GMATS, Wh + (size_t)(nBase + row) * DD + k0 + sC * 8);
        }
    };

    stage(0, 0);
    CP_COMMIT();

    for (int it = 0; it < 16; it++) {
        if (it < 15) {
            stage((it + 1) * 64, (it + 1) & 1);
            CP_COMMIT();
            CP_WAIT1();
        } else {
            CP_WAIT0();
        }
        __syncthreads();

        const uint32_t sb = s0 + (uint32_t)((it & 1) * GSTAGE);
        const uint32_t sA = sb, sB = sb + GMATS;

#pragma unroll
        for (int ks = 0; ks < 4; ks++) {
            const uint32_t acol = (uint32_t)((ks * 16 + (mat >> 1) * 8) * 2);
            uint32_t ah[2][4];
#pragma unroll
            for (int bm = 0; bm < 2; bm++) {
                const uint32_t ra = (uint32_t)((wm * 32 + bm * 16 + (mat & 1) * 8 + rin) * GPITCH);
                LDSM4(ah[bm][0], ah[bm][1], ah[bm][2], ah[bm][3], sA + ra + acol);
            }
            const uint32_t bcol = (uint32_t)((ks * 16 + (mat & 1) * 8) * 2);
            uint32_t bh[4][4];
#pragma unroll
            for (int bn = 0; bn < 4; bn++) {
                const uint32_t rb = (uint32_t)((wn * 64 + bn * 16 + (mat >> 1) * 8 + rin) * GPITCH);
                LDSM4(bh[bn][0], bh[bn][1], bh[bn][2], bh[bn][3], sB + rb + bcol);
            }
#pragma unroll
            for (int bn = 0; bn < 4; bn++)
#pragma unroll
                for (int bm = 0; bm < 2; bm++)
#pragma unroll
                    for (int nf = 0; nf < 2; nf++)
                        MMA_F16(acc[bm][bn * 2 + nf], ah[bm], bh[bn][nf * 2], bh[bn][nf * 2 + 1]);
        }
        __syncthreads();
    }

    const int g = lane >> 2;
    const int t2 = (lane & 3) * 2;
#pragma unroll
    for (int bm = 0; bm < 2; bm++) {
#pragma unroll
        for (int nf = 0; nf < 8; nf++) {
            const int n0 = nBase + wn * 64 + nf * 8 + t2;
            const float b0 = bias[n0], b1 = bias[n0 + 1];
#pragma unroll
            for (int half_ = 0; half_ < 2; half_++) {
                const int m = mBase + wm * 32 + bm * 16 + g + half_ * 8;
                float v0 = acc[bm][nf][half_ * 2 + 0] + b0;
                float v1 = acc[bm][nf][half_ * 2 + 1] + b1;
                if (WHICH < 3) {
                    if (WHICH == 0) { v0 *= 0.125f; v1 *= 0.125f; }
                    const int bI = m >> 11;
                    const int s = m & (SS - 1);
                    const int h = n0 >> 6;
                    const int dh = n0 & 63;
                    const size_t idx = (((size_t)(bI * HH + h)) * SS + s) * DHH + dh;
                    __half* dst = (WHICH == 0) ? gQh : (WHICH == 1) ? gKh : gVh;
                    *(uint32_t*)(dst + idx) = pack_f16(v0, v1);
                } else {
                    const size_t off = (size_t)m * DD + n0;
                    float2 rv = *(const float2*)(resid + off);
                    float2 t; t.x = v0 + rv.x; t.y = v1 + rv.y;
                    *(float2*)(g_res + off) = t;
                }
            }
        }
    }
}

__global__ __launch_bounds__(256, 2) void hmma_gemm_qkv(const float* __restrict__ bQ,
                                                        const float* __restrict__ bK,
                                                        const float* __restrict__ bV) {
    if (blockIdx.z == 0)      gemm_core<0>(gXh[0], gWh[0], bQ, nullptr);
    else if (blockIdx.z == 1) gemm_core<1>(gXh[1], gWh[1], bK, nullptr);
    else                      gemm_core<2>(gXh[2], gWh[2], bV, nullptr);
}

__global__ __launch_bounds__(256, 2) void hmma_gemm_o(const float* __restrict__ bO,
                                                      const float* __restrict__ resid) {
    gemm_core<3>(gCh, gWh[3], bO, resid);
}

// ---------------------------------------------------------------------------
// HMMA flash attention (causal), pure fp16 1-term, 64-key double-buffered
// (R13 version — measured fastest). 512 CTAs, 8 warps x 16 q-rows.
// ---------------------------------------------------------------------------
#define APITCH 144
#define ASTAGE (2 * 64 * APITCH)           /* 18432 B per stage: K + V */
#define ASMEM  (2 * ASTAGE)                /* 36864 B */

__global__ __launch_bounds__(256) void attn_mma_kernel() {
    extern __shared__ __align__(16) unsigned char dynsm[];
    const uint32_t base = smem_u32(dynsm);

    const int bh = blockIdx.x >> 4;
    const int qt = 15 - (blockIdx.x & 15);
    const int tid = threadIdx.x;
    const int lane = tid & 31;
    const int wid = tid >> 5;
    const int qBase = qt * 128;
    const int mat = lane >> 3;
    const int rin = lane & 7;
    const int g = lane >> 2;
    const int t2 = (lane & 3) * 2;

    const size_t headOff = (size_t)bh * SS * DHH;
    const int sRow = tid >> 3;            // 0..31
    const int sC = tid & 7;               // 16B chunk (8 halves) in 128B row

    // ---- prologue: stage Q (128 rows) across the buffer region ----
#pragma unroll
    for (int i = 0; i < 4; i++) {
        const int row = i * 32 + sRow;
        const uint32_t d = base + (uint32_t)(row * APITCH + sC * 16);
        cp16(d, gQh + headOff + (size_t)(qBase + row) * DHH + sC * 8);
    }
    CP_COMMIT();
    CP_WAIT0();
    __syncthreads();

    uint32_t qh[4][4];
#pragma unroll
    for (int kf = 0; kf < 4; kf++) {
        const uint32_t ra = (uint32_t)((wid * 16 + (mat & 1) * 8 + rin) * APITCH);
        const uint32_t acol = (uint32_t)((kf * 16 + (mat >> 1) * 8) * 2);
        LDSM4(qh[kf][0], qh[kf][1], qh[kf][2], qh[kf][3], base + ra + acol);
    }
    __syncthreads();                      // Q reads done; buffers free

    auto stageKV = [&](int c0, int buf) {
        const uint32_t sb = base + (uint32_t)(buf * ASTAGE);
#pragma unroll
        for (int i = 0; i < 2; i++) {
            const int row = i * 32 + sRow;
            const uint32_t d = sb + (uint32_t)(row * APITCH + sC * 16);
            const size_t off = headOff + (size_t)(c0 + row) * DHH + sC * 8;
            cp16(d,          gKh + off);
            cp16(d + 9216,   gVh + off);
        }
    };

    stageKV(0, 0);
    CP_COMMIT();

    float oacc[8][4];
#pragma unroll
    for (int f = 0; f < 8; f++)
#pragma unroll
        for (int c = 0; c < 4; c++) oacc[f][c] = 0.0f;
    float mA = -1e30f, mB = -1e30f, lA = 0.0f, lB = 0.0f;

    const int qw0 = qBase + wid * 16;
    const int nkc = 2 * qt + 2;

    for (int kc = 0; kc < nkc; kc++) {
        const int c0 = kc * 64;
        if (kc + 1 < nkc) {
            stageKV((kc + 1) * 64, (kc + 1) & 1);
            CP_COMMIT();
            CP_WAIT1();
        } else {
            CP_WAIT0();
        }
        __syncthreads();

        const uint32_t sb = base + (uint32_t)((kc & 1) * ASTAGE);
        const uint32_t Kh = sb, Vh = sb + 9216;

        if (c0 <= qw0 + 15) {
            // ---- S = Q * K^T ----
            float sacc[8][4];
#pragma unroll
            for (int f = 0; f < 8; f++)
#pragma unroll
                for (int c = 0; c < 4; c++) sacc[f][c] = 0.0f;

#pragma unroll
            for (int ks = 0; ks < 4; ks++) {
                const uint32_t bcol = (uint32_t)((ks * 16 + (mat & 1) * 8) * 2);
                uint32_t kbh[4][4];
#pragma unroll
                for (int bn = 0; bn < 4; bn++) {
                    const uint32_t rb = (uint32_t)((bn * 16 + (mat >> 1) * 8 + rin) * APITCH);
                    LDSM4(kbh[bn][0], kbh[bn][1], kbh[bn][2], kbh[bn][3], Kh + rb + bcol);
                }
#pragma unroll
                for (int bn = 0; bn < 4; bn++)
#pragma unroll
                    for (int nf = 0; nf < 2; nf++)
                        MMA_F16(sacc[bn * 2 + nf], qh[ks], kbh[bn][nf * 2], kbh[bn][nf * 2 + 1]);
            }

            // ---- causal mask ----
            const int rowA = qw0 + g;
            const int rowB = rowA + 8;
            if (c0 + 63 > qw0) {
#pragma unroll
                for (int f = 0; f < 8; f++) {
                    const int k0e = c0 + f * 8 + t2;
                    if (k0e > rowA)     sacc[f][0] = -1e30f;
                    if (k0e + 1 > rowA) sacc[f][1] = -1e30f;
                    if (k0e > rowB)     sacc[f][2] = -1e30f;
                    if (k0e + 1 > rowB) sacc[f][3] = -1e30f;
                }
            }

            // ---- online softmax ----
            float tmA = -1e30f, tmB = -1e30f;
#pragma unroll
            for (int f = 0; f < 8; f++) {
                tmA = fmaxf(tmA, fmaxf(sacc[f][0], sacc[f][1]));
                tmB = fmaxf(tmB, fmaxf(sacc[f][2], sacc[f][3]));
            }
            tmA = fmaxf(tmA, __shfl_xor_sync(0xffffffffu, tmA, 1));
            tmA = fmaxf(tmA, __shfl_xor_sync(0xffffffffu, tmA, 2));
            tmB = fmaxf(tmB, __shfl_xor_sync(0xffffffffu, tmB, 1));
            tmB = fmaxf(tmB, __shfl_xor_sync(0xffffffffu, tmB, 2));

            const float mnA = fmaxf(mA, tmA);
            const float mnB = fmaxf(mB, tmB);
            const float corrA = __expf(mA - mnA);
            const float corrB = __expf(mB - mnB);
            mA = mnA; mB = mnB;

            float sA = 0.0f, sB = 0.0f;
            uint32_t h01[8], h23[8];
#pragma unroll
            for (int f = 0; f < 8; f++) {
                float e0 = __expf(sacc[f][0] - mA);
                float e1 = __expf(sacc[f][1] - mA);
                float e2 = __expf(sacc[f][2] - mB);
                float e3 = __expf(sacc[f][3] - mB);
                sA += e0 + e1; sB += e2 + e3;
                h01[f] = pack_f16(e0, e1);
                h23[f] = pack_f16(e2, e3);
            }
            sA += __shfl_xor_sync(0xffffffffu, sA, 1);
            sA += __shfl_xor_sync(0xffffffffu, sA, 2);
            sB += __shfl_xor_sync(0xffffffffu, sB, 1);
            sB += __shfl_xor_sync(0xffffffffu, sB, 2);
            lA = lA * corrA + sA;
            lB = lB * corrB + sB;

#pragma unroll
            for (int f = 0; f < 8; f++) {
                oacc[f][0] *= corrA; oacc[f][1] *= corrA;
                oacc[f][2] *= corrB; oacc[f][3] *= corrB;
            }

            // ---- O += P * V ----
#pragma unroll
            for (int kf = 0; kf < 4; kf++) {
                uint32_t pah[4] = { h01[2 * kf], h23[2 * kf], h01[2 * kf + 1], h23[2 * kf + 1] };
                const uint32_t vaddr = (uint32_t)((kf * 16 + (lane & 15)) * APITCH +
                                                  ((lane >> 4) * 8) * 2);
                uint32_t vbh[4][4];
#pragma unroll
                for (int dhg = 0; dhg < 4; dhg++) {
                    const uint32_t va = vaddr + (uint32_t)(dhg * 32);
                    LDSM4T(vbh[dhg][0], vbh[dhg][1], vbh[dhg][2], vbh[dhg][3], Vh + va);
                }
#pragma unroll
                for (int dhg = 0; dhg < 4; dhg++)
#pragma unroll
                    for (int nf = 0; nf < 2; nf++)
                        MMA_F16(oacc[dhg * 2 + nf], pah, vbh[dhg][nf * 2], vbh[dhg][nf * 2 + 1]);
            }
        }
        __syncthreads();
    }

    // ---- epilogue: normalize, write ctx fp16 ----
    const float invA = 1.0f / lA;
    const float invB = 1.0f / lB;
    const int b = bh >> 4;
    const int h = bh & 15;
    const int rowA = qw0 + g;
#pragma unroll
    for (int f = 0; f < 8; f++) {
        const int dh0 = f * 8 + t2;
        {
            const size_t off = ((size_t)(b * SS) + rowA) * DD + h * 64 + dh0;
            *(uint32_t*)(gCh + off) = pack_f16(oacc[f][0] * invA, oacc[f][1] * invA);
        }
        {
            const size_t off = ((size_t)(b * SS) + rowA + 8) * DD + h * 64 + dh0;
            *(uint32_t*)(gCh + off) = pack_f16(oacc[f][2] * invB, oacc[f][3] * invB);
        }
    }
}

// ---------------------------------------------------------------------------
// LayerNorm over D=1024 per row (biased var).
// ---------------------------------------------------------------------------
__global__ __launch_bounds__(256) void ln_kernel(const float* __restrict__ gamma,
                                                 const float* __restrict__ beta,
                                                 float* __restrict__ out) {
    const int row = blockIdx.x;
    const int tid = threadIdx.x;
    const float4 v = ((const float4*)(g_res + (size_t)row * DD))[tid];

    float s = v.x + v.y + v.z + v.w;
    float ss = v.x * v.x + v.y * v.y + v.z * v.z + v.w * v.w;
#pragma unroll
    for (int off = 16; off > 0; off >>= 1) {
        s  += __shfl_xor_sync(0xffffffffu, s, off);
        ss += __shfl_xor_sync(0xffffffffu, ss, off);
    }
    __shared__ float sh[18];
    const int wid = tid >> 5;
    if ((tid & 31) == 0) { sh[wid] = s; sh[8 + wid] = ss; }
    __syncthreads();
    if (tid == 0) {
        float ts = 0.f, tss = 0.f;
#pragma unroll
        for (int w = 0; w < 8; w++) { ts += sh[w]; tss += sh[8 + w]; }
        const float mu = ts * (1.0f / DD);
        const float var = tss * (1.0f / DD) - mu * mu;
        sh[16] = mu;
        sh[17] = rsqrtf(var + 1e-5f);
    }
    __syncthreads();
    const float mu = sh[16];
    const float rstd = sh[17];

    const float4 gv = ((const float4*)gamma)[tid];
    const float4 bv = ((const float4*)beta)[tid];
    float4 r;
    r.x = (v.x - mu) * rstd * gv.x + bv.x;
    r.y = (v.y - mu) * rstd * gv.y + bv.y;
    r.z = (v.z - mu) * rstd * gv.z + bv.z;
    r.w = (v.w - mu) * rstd * gv.w + bv.w;
    ((float4*)(out + (size_t)row * DD))[tid] = r;
}

// ---------------------------------------------------------------------------
// 0 Q_source, 1 K_source, 2 V_source, 3 padding_mask, 4 future_mask,
// 5 WQ, 6 bQ, 7 WK, 8 bK, 9 WV, 10 bV, 11 WO, 12 bO, 13 gamma, 14 beta
// ---------------------------------------------------------------------------
extern "C" void kernel_launch(void* const* d_in, const int* in_sizes, int n_in,
                              void* d_out, int out_size) {
    (void)in_sizes; (void)n_in; (void)out_size;
    const float* Qs    = (const float*)d_in[0];
    const float* Ksrc  = (const float*)d_in[1];
    const float* Vsrc  = (const float*)d_in[2];
    const float* WQ    = (const float*)d_in[5];
    const float* bQ    = (const float*)d_in[6];
    const float* WK    = (const float*)d_in[7];
    const float* bK    = (const float*)d_in[8];
    const float* WV    = (const float*)d_in[9];
    const float* bV    = (const float*)d_in[10];
    const float* WO    = (const float*)d_in[11];
    const float* bO    = (const float*)d_in[12];
    const float* gamma = (const float*)d_in[13];
    const float* beta  = (const float*)d_in[14];

    static bool attrDone = false;
    if (!attrDone) {
        cudaFuncSetAttribute(hmma_gemm_qkv, cudaFuncAttributeMaxDynamicSharedMemorySize, GSMEM);
        cudaFuncSetAttribute(hmma_gemm_o,   cudaFuncAttributeMaxDynamicSharedMemorySize, GSMEM);
        cudaFuncSetAttribute(attn_mma_kernel, cudaFuncAttributeMaxDynamicSharedMemorySize, ASMEM);
        attrDone = true;
    }

    split_pass<<<dim3(MM * DD / 1024, 1, 7), 256>>>(Qs, Ksrc, Vsrc, WQ, WK, WV, WO);

    dim3 qkvGrid(DD / 128, MM / 128, 3);   // (8, 32, 3) = 768 CTAs
    hmma_gemm_qkv<<<qkvGrid, 256, GSMEM>>>(bQ, bK, bV);
    attn_mma_kernel<<<BB * HH * 16, 256, ASMEM>>>();
    hmma_gemm_o<<<dim3(DD / 128, MM / 128), 256, GSMEM>>>(bO, Qs);
    ln_kernel<<<MM, 256>>>(gamma, beta, (float*)d_out);
}